// round 11
// baseline (speedup 1.0000x reference)
#include <cuda_runtime.h>
#include <math.h>
#include <stdint.h>

#define T     8192
#define DIM   1024
#define NEXP  8
#define HID   2048

#define BM 128
#define BN 128
#define BK 16
#define ROWS_CAP (T * 2 + NEXP * 128)

// smem stage layout (bytes), static (identical to R10, proven):
#define RSA     48
#define RSB     272
#define ALO_D   6144
#define BHI_OFF 12288
#define BLO_D   4352
#define STAGEB  20992
// total static smem: 2*20992 = 41984 < 48K

// ---------------- scratch (__device__ globals) ------------------------------
__device__ float g_H[(size_t)ROWS_CAP * HID];   // 142.6 MB
__device__ int   g_tok[NEXP * T];
__device__ float g_wt[NEXP * T];
__device__ int   g_cnt[NEXP];
__device__ int   g_off[NEXP];

// ---------------- scalar helpers -------------------------------------------
__device__ __forceinline__ uint32_t smem_u32(const void* p) {
    uint32_t a;
    asm("{ .reg .u64 t; cvta.to.shared.u64 t, %1; cvt.u32.u64 %0, t; }"
        : "=r"(a) : "l"(p));
    return a;
}
__device__ __forceinline__ void cvt_hilo(float f0, float f1,
                                         uint32_t& hi, uint32_t& lo) {
    asm("cvt.rn.bf16x2.f32 %0, %1, %2;" : "=r"(hi) : "f"(f1), "f"(f0));
    float r0 = f0 - __uint_as_float(hi << 16);
    float r1 = f1 - __uint_as_float(hi & 0xffff0000u);
    asm("cvt.rn.bf16x2.f32 %0, %1, %2;" : "=r"(lo) : "f"(r1), "f"(r0));
}
#define STS128(addr, r0, r1, r2, r3)                                          \
    asm volatile("st.shared.v4.b32 [%0], {%1,%2,%3,%4};"                      \
                 :: "r"(addr), "r"(r0), "r"(r1), "r"(r2), "r"(r3) : "memory")
#define LDSM4(r0, r1, r2, r3, addr)                                           \
    asm volatile("ldmatrix.sync.aligned.m8n8.x4.shared.b16 {%0,%1,%2,%3}, [%4];" \
                 : "=r"(r0), "=r"(r1), "=r"(r2), "=r"(r3) : "r"(addr))
#define LDSM4T(r0, r1, r2, r3, addr)                                          \
    asm volatile("ldmatrix.sync.aligned.m8n8.x4.trans.shared.b16 {%0,%1,%2,%3}, [%4];" \
                 : "=r"(r0), "=r"(r1), "=r"(r2), "=r"(r3) : "r"(addr))
#define MMA4(c0,c1,c2,c3, a0,a1,a2,a3, b0,b1)                                 \
    asm volatile(                                                             \
        "mma.sync.aligned.m16n8k16.row.col.f32.bf16.bf16.f32 "                \
        "{%0,%1,%2,%3}, {%4,%5,%6,%7}, {%8,%9}, {%0,%1,%2,%3};"               \
        : "+f"(c0), "+f"(c1), "+f"(c2), "+f"(c3)                              \
        : "r"(a0), "r"(a1), "r"(a2), "r"(a3), "r"(b0), "r"(b1))

#define GELU(v) (0.5f * (v) * (1.0f + erff((v) * 0.7071067811865476f)))

// accumulators d{M}{J}_{0..3}: M = m16 tile 0..3, J = n8 tile 0..7
#define DECL4(p) float p##_0 = 0.f, p##_1 = 0.f, p##_2 = 0.f, p##_3 = 0.f

// one m16 row across 8 n8 tiles (8 MMA4)
#define TROW(M, A0,A1,A2,A3, B0,B1,B2,B3,B4,B5,B6,B7,B8,B9,BA,BB,BC,BD,BE,BF) \
    MMA4(d##M##0_0,d##M##0_1,d##M##0_2,d##M##0_3, A0,A1,A2,A3, B0,B1);        \
    MMA4(d##M##1_0,d##M##1_1,d##M##1_2,d##M##1_3, A0,A1,A2,A3, B2,B3);        \
    MMA4(d##M##2_0,d##M##2_1,d##M##2_2,d##M##2_3, A0,A1,A2,A3, B4,B5);        \
    MMA4(d##M##3_0,d##M##3_1,d##M##3_2,d##M##3_3, A0,A1,A2,A3, B6,B7);        \
    MMA4(d##M##4_0,d##M##4_1,d##M##4_2,d##M##4_3, A0,A1,A2,A3, B8,B9);        \
    MMA4(d##M##5_0,d##M##5_1,d##M##5_2,d##M##5_3, A0,A1,A2,A3, BA,BB);        \
    MMA4(d##M##6_0,d##M##6_1,d##M##6_2,d##M##6_3, A0,A1,A2,A3, BC,BD);        \
    MMA4(d##M##7_0,d##M##7_1,d##M##7_2,d##M##7_3, A0,A1,A2,A3, BE,BF)

// full 64x64 term: 32 MMA4
#define TERMX(B0,B1,B2,B3,B4,B5,B6,B7,B8,B9,BA,BB,BC,BD,BE,BF)                \
    TROW(0, ah0,ah1,ah2,ah3, B0,B1,B2,B3,B4,B5,B6,B7,B8,B9,BA,BB,BC,BD,BE,BF);\
    TROW(1, ah4,ah5,ah6,ah7, B0,B1,B2,B3,B4,B5,B6,B7,B8,B9,BA,BB,BC,BD,BE,BF);\
    TROW(2, ah8,ah9,aha,ahb, B0,B1,B2,B3,B4,B5,B6,B7,B8,B9,BA,BB,BC,BD,BE,BF);\
    TROW(3, ahc,ahd,ahe,ahf, B0,B1,B2,B3,B4,B5,B6,B7,B8,B9,BA,BB,BC,BD,BE,BF)

// ---------------------------------------------------------------------------
// Zero output + expert counters
// ---------------------------------------------------------------------------
__global__ void zero_kernel(float* __restrict__ out) {
    size_t i = (size_t)blockIdx.x * blockDim.x + threadIdx.x;
    const size_t n4 = (size_t)T * DIM / 4;
    float4 z = make_float4(0.f, 0.f, 0.f, 0.f);
    for (size_t p = i; p < n4; p += (size_t)gridDim.x * blockDim.x)
        reinterpret_cast<float4*>(out)[p] = z;
    if (i < NEXP) g_cnt[i] = 0;
}

// ---------------------------------------------------------------------------
// Gating: 1 warp/token, logits + top-2 + compaction
// ---------------------------------------------------------------------------
__global__ __launch_bounds__(256) void gate_kernel(
    const float* __restrict__ x, const float* __restrict__ gw,
    const float* __restrict__ gb, float* __restrict__ logits_out)
{
    int warp = (int)((blockIdx.x * blockDim.x + threadIdx.x) >> 5);
    int lane = threadIdx.x & 31;
    if (warp >= T) return;

    const float4* xr = reinterpret_cast<const float4*>(x + (size_t)warp * DIM);
    float acc[NEXP];
#pragma unroll
    for (int e = 0; e < NEXP; e++) acc[e] = 0.f;

    for (int i = lane; i < DIM / 4; i += 32) {
        float4 xv = xr[i];
#pragma unroll
        for (int e = 0; e < NEXP; e++) {
            float4 wv = reinterpret_cast<const float4*>(gw + (size_t)e * DIM)[i];
            acc[e] += xv.x * wv.x + xv.y * wv.y + xv.z * wv.z + xv.w * wv.w;
        }
    }
#pragma unroll
    for (int off = 16; off > 0; off >>= 1)
#pragma unroll
        for (int e = 0; e < NEXP; e++)
            acc[e] += __shfl_xor_sync(0xffffffffu, acc[e], off);

    if (lane == 0) {
        float lg[NEXP];
#pragma unroll
        for (int e = 0; e < NEXP; e++) lg[e] = acc[e] + gb[e];

        int i0 = 0;
#pragma unroll
        for (int e = 1; e < NEXP; e++) if (lg[e] > lg[i0]) i0 = e;
        int i1 = (i0 == 0) ? 1 : 0;
#pragma unroll
        for (int e = 0; e < NEXP; e++)
            if (e != i0 && lg[e] > lg[i1]) i1 = e;

        float w0 = 1.0f / (1.0f + expf(lg[i1] - lg[i0]));
        float w1 = 1.0f - w0;

        int s0 = atomicAdd(&g_cnt[i0], 1);
        g_tok[i0 * T + s0] = warp;  g_wt[i0 * T + s0] = w0;
        int s1 = atomicAdd(&g_cnt[i1], 1);
        g_tok[i1 * T + s1] = warp;  g_wt[i1 * T + s1] = w1;

#pragma unroll
        for (int e = 0; e < NEXP; e++)
            logits_out[(size_t)warp * NEXP + e] = lg[e];
    }
}

__global__ void offsets_kernel() {
    if (threadIdx.x == 0 && blockIdx.x == 0) {
        int off = 0;
        for (int e = 0; e < NEXP; e++) {
            g_off[e] = off;
            off += ((g_cnt[e] + 127) / 128) * 128;
        }
    }
}

// ---------------------------------------------------------------------------
// MoE GEMM, warp-specialized: warps 0-3 compute (64x64 tiles), warps 4-7 load
// (LDG fp32 -> in-register bf16 hi/lo split -> STS). 2-stage double buffer,
// static smem, 3-term precision split. CTA tile 128x128, BK=16.
// ---------------------------------------------------------------------------
template<bool FFN1>
__global__ __launch_bounds__(256) void moe_mma(
    const float* __restrict__ x, const float* __restrict__ W,
    const float* __restrict__ bias, float* __restrict__ out)
{
    constexpr int KTOT = FFN1 ? DIM : HID;
    constexpr int NTOT = FFN1 ? HID : DIM;
    constexpr int NCH  = KTOT / BK;

    int e   = blockIdx.z;
    int cnt = g_cnt[e];
    int m0  = blockIdx.y * BM;
    if (m0 >= cnt) return;
    int n0   = blockIdx.x * BN;
    int base = g_off[e];

    __shared__ __align__(128) char smem[2][STAGEB];
    uint32_t sbase = smem_u32(&smem[0][0]);

    int tid = threadIdx.x, lane = tid & 31, wid = tid >> 5;
    bool loader = (wid >= 4);

    // ---------------- loader state (warps 4-7: 128 threads) ----------------
    const float *pA = nullptr, *pB = nullptr;
    uint32_t aoff = 0, boff = 0;
    if (loader) {
        int u = tid - 128;                       // 0..127
        // A role: one full row (16 floats) per thread
        if (FFN1) {
            int gm  = m0 + u;
            int tok = g_tok[e * T + (gm < cnt ? gm : cnt - 1)];
            pA = x + (size_t)tok * DIM;
        } else {
            pA = g_H + (size_t)(base + m0 + u) * HID;
        }
        aoff = (uint32_t)(u * RSA);
        // B role: krow = u>>3 (0..15), seg = u&7 (16 n-floats)
        int krow = u >> 3, seg = u & 7;
        pB = W + ((size_t)e * KTOT + krow) * NTOT + n0 + seg * 16;
        boff = (uint32_t)(BHI_OFF + krow * RSB + seg * 32);
    }
    float4 va0, va1, va2, va3, vb0, vb1, vb2, vb3;

#define LOADR do {                                                            \
        va0 = *(const float4*)pA;       va1 = *(const float4*)(pA + 4);       \
        va2 = *(const float4*)(pA + 8); va3 = *(const float4*)(pA + 12);      \
        vb0 = *(const float4*)pB;       vb1 = *(const float4*)(pB + 4);       \
        vb2 = *(const float4*)(pB + 8); vb3 = *(const float4*)(pB + 12);      \
        pA += BK;  pB += (size_t)BK * NTOT;                                   \
    } while (0)

#define STSSTAGE(b) do {                                                      \
        uint32_t s_ = sbase + (uint32_t)((b) * STAGEB);                       \
        uint32_t h0,h1,h2,h3,h4,h5,h6,h7, l0,l1,l2,l3,l4,l5,l6,l7;            \
        cvt_hilo(va0.x, va0.y, h0, l0);  cvt_hilo(va0.z, va0.w, h1, l1);      \
        cvt_hilo(va1.x, va1.y, h2, l2);  cvt_hilo(va1.z, va1.w, h3, l3);      \
        cvt_hilo(va2.x, va2.y, h4, l4);  cvt_hilo(va2.z, va2.w, h5, l5);      \
        cvt_hilo(va3.x, va3.y, h6, l6);  cvt_hilo(va3.z, va3.w, h7, l7);      \
        STS128(s_ + aoff,              h0, h1, h2, h3);                       \
        STS128(s_ + aoff + 16,         h4, h5, h6, h7);                       \
        STS128(s_ + aoff + ALO_D,      l0, l1, l2, l3);                       \
        STS128(s_ + aoff + ALO_D + 16, l4, l5, l6, l7);                       \
        cvt_hilo(vb0.x, vb0.y, h0, l0);  cvt_hilo(vb0.z, vb0.w, h1, l1);      \
        cvt_hilo(vb1.x, vb1.y, h2, l2);  cvt_hilo(vb1.z, vb1.w, h3, l3);      \
        cvt_hilo(vb2.x, vb2.y, h4, l4);  cvt_hilo(vb2.z, vb2.w, h5, l5);      \
        cvt_hilo(vb3.x, vb3.y, h6, l6);  cvt_hilo(vb3.z, vb3.w, h7, l7);      \
        STS128(s_ + boff,              h0, h1, h2, h3);                       \
        STS128(s_ + boff + 16,         h4, h5, h6, h7);                       \
        STS128(s_ + boff + BLO_D,      l0, l1, l2, l3);                       \
        STS128(s_ + boff + BLO_D + 16, l4, l5, l6, l7);                       \
    } while (0)

    // ---------------- compute state (warps 0-3) -----------------------------
    int wm = wid >> 1, wn = wid & 1;             // 2x2 warp grid, 64x64 tiles
    uint32_t apos = (uint32_t)((wm * 64 + (lane & 15)) * RSA + (lane >> 4) * 16);
    uint32_t bpos = (uint32_t)(BHI_OFF + (lane & 15) * RSB + (lane >> 4) * 16
                               + wn * 128);

    DECL4(d00); DECL4(d01); DECL4(d02); DECL4(d03);
    DECL4(d04); DECL4(d05); DECL4(d06); DECL4(d07);
    DECL4(d10); DECL4(d11); DECL4(d12); DECL4(d13);
    DECL4(d14); DECL4(d15); DECL4(d16); DECL4(d17);
    DECL4(d20); DECL4(d21); DECL4(d22); DECL4(d23);
    DECL4(d24); DECL4(d25); DECL4(d26); DECL4(d27);
    DECL4(d30); DECL4(d31); DECL4(d32); DECL4(d33);
    DECL4(d34); DECL4(d35); DECL4(d36); DECL4(d37);

    uint32_t ah0,ah1,ah2,ah3, ah4,ah5,ah6,ah7;
    uint32_t ah8,ah9,aha,ahb, ahc,ahd,ahe,ahf;
    uint32_t bh0,bh1,bh2,bh3, bh4,bh5,bh6,bh7;
    uint32_t bh8,bh9,bha,bhb, bhc,bhd,bhe,bhf;
    uint32_t bl0,bl1,bl2,bl3, bl4,bl5,bl6,bl7;
    uint32_t bl8,bl9,bla,blb, blc,bld,ble,blf;

#define KSTEP(sb_) do {                                                       \
        uint32_t aA_ = (sb_) + apos;                                          \
        uint32_t aB_ = (sb_) + bpos;                                          \
        LDSM4 (ah0,ah1,ah2,ah3, aA_);                                         \
        LDSM4 (ah4,ah5,ah6,ah7, aA_ + 16 * RSA);                              \
        LDSM4 (ah8,ah9,aha,ahb, aA_ + 32 * RSA);                              \
        LDSM4 (ahc,ahd,ahe,ahf, aA_ + 48 * RSA);                              \
        LDSM4T(bh0,bh1,bh2,bh3, aB_);                                         \
        LDSM4T(bh4,bh5,bh6,bh7, aB_ + 32);                                    \
        LDSM4T(bh8,bh9,bha,bhb, aB_ + 64);                                    \
        LDSM4T(bhc,bhd,bhe,bhf, aB_ + 96);                                    \
        LDSM4T(bl0,bl1,bl2,bl3, aB_ + BLO_D);                                 \
        LDSM4T(bl4,bl5,bl6,bl7, aB_ + BLO_D + 32);                            \
        LDSM4T(bl8,bl9,bla,blb, aB_ + BLO_D + 64);                            \
        LDSM4T(blc,bld,ble,blf, aB_ + BLO_D + 96);                            \
        TERMX(bh0,bh1,bh2,bh3,bh4,bh5,bh6,bh7,                                \
              bh8,bh9,bha,bhb,bhc,bhd,bhe,bhf);                               \
        TERMX(bl0,bl1,bl2,bl3,bl4,bl5,bl6,bl7,                                \
              bl8,bl9,bla,blb,blc,bld,ble,blf);                               \
        LDSM4 (ah0,ah1,ah2,ah3, aA_ + ALO_D);                                 \
        LDSM4 (ah4,ah5,ah6,ah7, aA_ + ALO_D + 16 * RSA);                      \
        LDSM4 (ah8,ah9,aha,ahb, aA_ + ALO_D + 32 * RSA);                      \
        LDSM4 (ahc,ahd,ahe,ahf, aA_ + ALO_D + 48 * RSA);                      \
        TERMX(bh0,bh1,bh2,bh3,bh4,bh5,bh6,bh7,                                \
              bh8,bh9,bha,bhb,bhc,bhd,bhe,bhf);                               \
    } while (0)

    // ---------------- pipeline ----------------------------------------------
    if (loader) {
        LOADR;            // chunk 0
        STSSTAGE(0);
        LOADR;            // chunk 1 held in regs
    }
    __syncthreads();

#pragma unroll 1
    for (int c = 0; c < NCH; c++) {
        if (loader) {
            if (c + 1 < NCH) STSSTAGE((c + 1) & 1);
            if (c + 2 < NCH) LOADR;
        } else {
            KSTEP(sbase + (uint32_t)((c & 1) * STAGEB));
        }
        __syncthreads();
    }
#undef KSTEP
#undef STSSTAGE
#undef LOADR

    if (loader) return;

    // ---------------- epilogue (compute warps only) -------------------------
    int grp = lane >> 2, qid = lane & 3;
    int r0 = m0 + wm * 64 + grp;
    int colB = n0 + wn * 64 + qid * 2;
    const float* bvec = bias + (size_t)e * NTOT;

    if (FFN1) {
#define EP1(M, J) do {                                                        \
        int col_ = colB + (J) * 8;                                            \
        float b0_ = __ldg(bvec + col_), b1_ = __ldg(bvec + col_ + 1);         \
        int rL_ = r0 + (M) * 16;                                              \
        if (rL_ < cnt) {                                                      \
            float u0 = d##M##J##_0 + b0_, u1 = d##M##J##_1 + b1_;             \
            *(float2*)(g_H + (size_t)(base + rL_) * HID + col_) =             \
                make_float2(GELU(u0), GELU(u1));                              \
        }                                                                     \
        if (rL_ + 8 < cnt) {                                                  \
            float u0 = d##M##J##_2 + b0_, u1 = d##M##J##_3 + b1_;             \
            *(float2*)(g_H + (size_t)(base + rL_ + 8) * HID + col_) =         \
                make_float2(GELU(u0), GELU(u1));                              \
        }                                                                     \
    } while (0)
        EP1(0,0); EP1(0,1); EP1(0,2); EP1(0,3); EP1(0,4); EP1(0,5); EP1(0,6); EP1(0,7);
        EP1(1,0); EP1(1,1); EP1(1,2); EP1(1,3); EP1(1,4); EP1(1,5); EP1(1,6); EP1(1,7);
        EP1(2,0); EP1(2,1); EP1(2,2); EP1(2,3); EP1(2,4); EP1(2,5); EP1(2,6); EP1(2,7);
        EP1(3,0); EP1(3,1); EP1(3,2); EP1(3,3); EP1(3,4); EP1(3,5); EP1(3,6); EP1(3,7);
#undef EP1
    } else {
#define EP2(M, J, TK, WW, TKH, WWH) do {                                      \
        int col_ = colB + (J) * 8;                                            \
        float b0_ = __ldg(bvec + col_), b1_ = __ldg(bvec + col_ + 1);         \
        int rL_ = r0 + (M) * 16;                                              \
        if (rL_ < cnt) {                                                      \
            atomicAdd(out + (size_t)(TK) * DIM + col_,     (d##M##J##_0 + b0_) * (WW)); \
            atomicAdd(out + (size_t)(TK) * DIM + col_ + 1, (d##M##J##_1 + b1_) * (WW)); \
        }                                                                     \
        if (rL_ + 8 < cnt) {                                                  \
            atomicAdd(out + (size_t)(TKH) * DIM + col_,     (d##M##J##_2 + b0_) * (WWH)); \
            atomicAdd(out + (size_t)(TKH) * DIM + col_ + 1, (d##M##J##_3 + b1_) * (WWH)); \
        }                                                                     \
    } while (0)
#define EPM(M) do {                                                           \
        int rL_ = r0 + (M) * 16;                                              \
        int tkL_ = 0, tkH_ = 0; float wL_ = 0.f, wH_ = 0.f;                   \
        if (rL_ < cnt)     { tkL_ = g_tok[e*T + rL_];     wL_ = g_wt[e*T + rL_]; } \
        if (rL_ + 8 < cnt) { tkH_ = g_tok[e*T + rL_ + 8]; wH_ = g_wt[e*T + rL_ + 8]; } \
        EP2(M,0,tkL_,wL_,tkH_,wH_); EP2(M,1,tkL_,wL_,tkH_,wH_);               \
        EP2(M,2,tkL_,wL_,tkH_,wH_); EP2(M,3,tkL_,wL_,tkH_,wH_);               \
        EP2(M,4,tkL_,wL_,tkH_,wH_); EP2(M,5,tkL_,wL_,tkH_,wH_);               \
        EP2(M,6,tkL_,wL_,tkH_,wH_); EP2(M,7,tkL_,wL_,tkH_,wH_);               \
    } while (0)
        EPM(0); EPM(1); EPM(2); EPM(3);
#undef EPM
#undef EP2
    }
}

// ---------------------------------------------------------------------------
// Launch
// ---------------------------------------------------------------------------
extern "C" void kernel_launch(void* const* d_in, const int* in_sizes, int n_in,
                              void* d_out, int out_size) {
    const float* x  = (const float*)d_in[0];
    const float* gw = (const float*)d_in[1];
    const float* gb = (const float*)d_in[2];
    const float* W1 = (const float*)d_in[3];
    const float* b1 = (const float*)d_in[4];
    const float* W2 = (const float*)d_in[5];
    const float* b2 = (const float*)d_in[6];
    float* out = (float*)d_out;

    zero_kernel<<<2048, 256>>>(out);
    gate_kernel<<<T / 8, 256>>>(x, gw, gb, out + (size_t)T * DIM);
    offsets_kernel<<<1, 32>>>();

    moe_mma<true ><<<dim3(HID / BN, T / BM, NEXP), 256>>>(x, W1, b1, nullptr);
    moe_mma<false><<<dim3(DIM / BN, T / BM, NEXP), 256>>>(nullptr, W2, b2, out);
}

// round 12
// speedup vs baseline: 1.1039x; 1.1039x over previous
#include <cuda_runtime.h>
#include <math.h>
#include <stdint.h>

#define T     8192
#define DIM   1024
#define NEXP  8
#define HID   2048

#define BM 128
#define BN 128
#define BK 16
#define ROWS_CAP (T * 2 + NEXP * 128)

// smem stage layout (bytes), static (R10-proven strides):
#define RSA     48
#define RSB     272
#define ALO_D   6144
#define BHI_OFF 12288
#define BLO_D   4352
#define STAGEB  20992
// total static smem: 2*20992 = 41984 < 48K

// ---------------- scratch (__device__ globals) ------------------------------
__device__ float g_H[(size_t)ROWS_CAP * HID];   // 142.6 MB
__device__ int   g_tok[NEXP * T];
__device__ float g_wt[NEXP * T];
__device__ int   g_cnt[NEXP];
__device__ int   g_off[NEXP];

// ---------------- scalar helpers -------------------------------------------
__device__ __forceinline__ uint32_t smem_u32(const void* p) {
    uint32_t a;
    asm("{ .reg .u64 t; cvta.to.shared.u64 t, %1; cvt.u32.u64 %0, t; }"
        : "=r"(a) : "l"(p));
    return a;
}
__device__ __forceinline__ void cvt_hilo(float f0, float f1,
                                         uint32_t& hi, uint32_t& lo) {
    asm("cvt.rn.bf16x2.f32 %0, %1, %2;" : "=r"(hi) : "f"(f1), "f"(f0));
    float r0 = f0 - __uint_as_float(hi << 16);
    float r1 = f1 - __uint_as_float(hi & 0xffff0000u);
    asm("cvt.rn.bf16x2.f32 %0, %1, %2;" : "=r"(lo) : "f"(r1), "f"(r0));
}
#define STS128(addr, r0, r1, r2, r3)                                          \
    asm volatile("st.shared.v4.b32 [%0], {%1,%2,%3,%4};"                      \
                 :: "r"(addr), "r"(r0), "r"(r1), "r"(r2), "r"(r3) : "memory")
#define LDSM4(r0, r1, r2, r3, addr)                                           \
    asm volatile("ldmatrix.sync.aligned.m8n8.x4.shared.b16 {%0,%1,%2,%3}, [%4];" \
                 : "=r"(r0), "=r"(r1), "=r"(r2), "=r"(r3) : "r"(addr))
#define LDSM4T(r0, r1, r2, r3, addr)                                          \
    asm volatile("ldmatrix.sync.aligned.m8n8.x4.trans.shared.b16 {%0,%1,%2,%3}, [%4];" \
                 : "=r"(r0), "=r"(r1), "=r"(r2), "=r"(r3) : "r"(addr))
#define MMA4(c0,c1,c2,c3, a0,a1,a2,a3, b0,b1)                                 \
    asm volatile(                                                             \
        "mma.sync.aligned.m16n8k16.row.col.f32.bf16.bf16.f32 "                \
        "{%0,%1,%2,%3}, {%4,%5,%6,%7}, {%8,%9}, {%0,%1,%2,%3};"               \
        : "+f"(c0), "+f"(c1), "+f"(c2), "+f"(c3)                              \
        : "r"(a0), "r"(a1), "r"(a2), "r"(a3), "r"(b0), "r"(b1))

#define GELU(v) (0.5f * (v) * (1.0f + erff((v) * 0.7071067811865476f)))

#define DECL4(p) float p##_0 = 0.f, p##_1 = 0.f, p##_2 = 0.f, p##_3 = 0.f

// one m16 row across 8 n8 tiles (8 MMA4), fragments FA/FB
#define TROW(M, A0,A1,A2,A3)                                                  \
    MMA4(d##M##0_0,d##M##0_1,d##M##0_2,d##M##0_3, A0,A1,A2,A3, fb0,fb1);      \
    MMA4(d##M##1_0,d##M##1_1,d##M##1_2,d##M##1_3, A0,A1,A2,A3, fb2,fb3);      \
    MMA4(d##M##2_0,d##M##2_1,d##M##2_2,d##M##2_3, A0,A1,A2,A3, fb4,fb5);      \
    MMA4(d##M##3_0,d##M##3_1,d##M##3_2,d##M##3_3, A0,A1,A2,A3, fb6,fb7);      \
    MMA4(d##M##4_0,d##M##4_1,d##M##4_2,d##M##4_3, A0,A1,A2,A3, fb8,fb9);      \
    MMA4(d##M##5_0,d##M##5_1,d##M##5_2,d##M##5_3, A0,A1,A2,A3, fba,fbb);      \
    MMA4(d##M##6_0,d##M##6_1,d##M##6_2,d##M##6_3, A0,A1,A2,A3, fbc,fbd);      \
    MMA4(d##M##7_0,d##M##7_1,d##M##7_2,d##M##7_3, A0,A1,A2,A3, fbe,fbf)

// full 64x64 term using current FA/FB contents (32 MMA4)
#define TERMX()                                                               \
    TROW(0, fa0,fa1,fa2,fa3);                                                 \
    TROW(1, fa4,fa5,fa6,fa7);                                                 \
    TROW(2, fa8,fa9,faa,fab);                                                 \
    TROW(3, fac,fad,fae,faf)

// ---------------------------------------------------------------------------
// Zero output + expert counters
// ---------------------------------------------------------------------------
__global__ void zero_kernel(float* __restrict__ out) {
    size_t i = (size_t)blockIdx.x * blockDim.x + threadIdx.x;
    const size_t n4 = (size_t)T * DIM / 4;
    float4 z = make_float4(0.f, 0.f, 0.f, 0.f);
    for (size_t p = i; p < n4; p += (size_t)gridDim.x * blockDim.x)
        reinterpret_cast<float4*>(out)[p] = z;
    if (i < NEXP) g_cnt[i] = 0;
}

// ---------------------------------------------------------------------------
// Gating: 1 warp/token, logits + top-2 + compaction
// ---------------------------------------------------------------------------
__global__ __launch_bounds__(256) void gate_kernel(
    const float* __restrict__ x, const float* __restrict__ gw,
    const float* __restrict__ gb, float* __restrict__ logits_out)
{
    int warp = (int)((blockIdx.x * blockDim.x + threadIdx.x) >> 5);
    int lane = threadIdx.x & 31;
    if (warp >= T) return;

    const float4* xr = reinterpret_cast<const float4*>(x + (size_t)warp * DIM);
    float acc[NEXP];
#pragma unroll
    for (int e = 0; e < NEXP; e++) acc[e] = 0.f;

    for (int i = lane; i < DIM / 4; i += 32) {
        float4 xv = xr[i];
#pragma unroll
        for (int e = 0; e < NEXP; e++) {
            float4 wv = reinterpret_cast<const float4*>(gw + (size_t)e * DIM)[i];
            acc[e] += xv.x * wv.x + xv.y * wv.y + xv.z * wv.z + xv.w * wv.w;
        }
    }
#pragma unroll
    for (int off = 16; off > 0; off >>= 1)
#pragma unroll
        for (int e = 0; e < NEXP; e++)
            acc[e] += __shfl_xor_sync(0xffffffffu, acc[e], off);

    if (lane == 0) {
        float lg[NEXP];
#pragma unroll
        for (int e = 0; e < NEXP; e++) lg[e] = acc[e] + gb[e];

        int i0 = 0;
#pragma unroll
        for (int e = 1; e < NEXP; e++) if (lg[e] > lg[i0]) i0 = e;
        int i1 = (i0 == 0) ? 1 : 0;
#pragma unroll
        for (int e = 0; e < NEXP; e++)
            if (e != i0 && lg[e] > lg[i1]) i1 = e;

        float w0 = 1.0f / (1.0f + expf(lg[i1] - lg[i0]));
        float w1 = 1.0f - w0;

        int s0 = atomicAdd(&g_cnt[i0], 1);
        g_tok[i0 * T + s0] = warp;  g_wt[i0 * T + s0] = w0;
        int s1 = atomicAdd(&g_cnt[i1], 1);
        g_tok[i1 * T + s1] = warp;  g_wt[i1 * T + s1] = w1;

#pragma unroll
        for (int e = 0; e < NEXP; e++)
            logits_out[(size_t)warp * NEXP + e] = lg[e];
    }
}

__global__ void offsets_kernel() {
    if (threadIdx.x == 0 && blockIdx.x == 0) {
        int off = 0;
        for (int e = 0; e < NEXP; e++) {
            g_off[e] = off;
            off += ((g_cnt[e] + 127) / 128) * 128;
        }
    }
}

// ---------------------------------------------------------------------------
// MoE GEMM: 128 threads, 4 warps (2x2), warp tile 64x64, CTA 128x128, BK=16.
// 3-term hi/lo split ordered T2(Ahi*Blo) -> T1(Ahi*Bhi) -> T3(Alo*Bhi) so frag
// peak = 32 regs (two 16-reg buffers). Split-phase loader (A then B) keeps
// staging at 16 regs. 2-stage static smem double buffer.
// ---------------------------------------------------------------------------
template<bool FFN1>
__global__ __launch_bounds__(128) void moe_mma(
    const float* __restrict__ x, const float* __restrict__ W,
    const float* __restrict__ bias, float* __restrict__ out)
{
    constexpr int KTOT = FFN1 ? DIM : HID;
    constexpr int NTOT = FFN1 ? HID : DIM;
    constexpr int NCH  = KTOT / BK;

    int e   = blockIdx.z;
    int cnt = g_cnt[e];
    int m0  = blockIdx.y * BM;
    if (m0 >= cnt) return;
    int n0   = blockIdx.x * BN;
    int base = g_off[e];

    __shared__ __align__(128) char smem[2][STAGEB];
    uint32_t sbase = smem_u32(&smem[0][0]);

    int tid = threadIdx.x, lane = tid & 31, wid = tid >> 5;

    // ---- loader state: thread u owns A row u and B (krow=u>>3, seg=u&7) ----
    const float *pA, *pB;
    {
        int u = tid;
        if (FFN1) {
            int gm  = m0 + u;
            int tok = g_tok[e * T + (gm < cnt ? gm : cnt - 1)];
            pA = x + (size_t)tok * DIM;
        } else {
            pA = g_H + (size_t)(base + m0 + u) * HID;
        }
        int krow = u >> 3, seg = u & 7;
        pB = W + ((size_t)e * KTOT + krow) * NTOT + n0 + seg * 16;
    }
    uint32_t aoff = (uint32_t)(tid * RSA);
    uint32_t boff = (uint32_t)(BHI_OFF + (tid >> 3) * RSB + (tid & 7) * 32);

    float4 va0, va1, va2, va3;           // shared staging for A-phase / B-phase

#define LOADR_A do {                                                          \
        va0 = *(const float4*)pA;       va1 = *(const float4*)(pA + 4);       \
        va2 = *(const float4*)(pA + 8); va3 = *(const float4*)(pA + 12);      \
        pA += BK;                                                             \
    } while (0)
#define LOADR_B do {                                                          \
        va0 = *(const float4*)pB;       va1 = *(const float4*)(pB + 4);       \
        va2 = *(const float4*)(pB + 8); va3 = *(const float4*)(pB + 12);      \
        pB += (size_t)BK * NTOT;                                              \
    } while (0)
#define STS_X(s_, off_, lodelta_) do {                                        \
        uint32_t h0,h1,h2,h3, l0,l1,l2,l3;                                    \
        cvt_hilo(va0.x, va0.y, h0, l0);  cvt_hilo(va0.z, va0.w, h1, l1);      \
        cvt_hilo(va1.x, va1.y, h2, l2);  cvt_hilo(va1.z, va1.w, h3, l3);      \
        STS128((s_) + (off_),              h0, h1, h2, h3);                   \
        STS128((s_) + (off_) + (lodelta_), l0, l1, l2, l3);                   \
        cvt_hilo(va2.x, va2.y, h0, l0);  cvt_hilo(va2.z, va2.w, h1, l1);      \
        cvt_hilo(va3.x, va3.y, h2, l2);  cvt_hilo(va3.z, va3.w, h3, l3);      \
        STS128((s_) + (off_) + 16,              h0, h1, h2, h3);              \
        STS128((s_) + (off_) + (lodelta_) + 16, l0, l1, l2, l3);              \
    } while (0)

    // ---- compute state ------------------------------------------------------
    int wm = wid >> 1, wn = wid & 1;
    uint32_t apos = (uint32_t)((wm * 64 + (lane & 15)) * RSA + (lane >> 4) * 16);
    uint32_t bpos = (uint32_t)(BHI_OFF + (lane & 15) * RSB + (lane >> 4) * 16
                               + wn * 128);

    DECL4(d00); DECL4(d01); DECL4(d02); DECL4(d03);
    DECL4(d04); DECL4(d05); DECL4(d06); DECL4(d07);
    DECL4(d10); DECL4(d11); DECL4(d12); DECL4(d13);
    DECL4(d14); DECL4(d15); DECL4(d16); DECL4(d17);
    DECL4(d20); DECL4(d21); DECL4(d22); DECL4(d23);
    DECL4(d24); DECL4(d25); DECL4(d26); DECL4(d27);
    DECL4(d30); DECL4(d31); DECL4(d32); DECL4(d33);
    DECL4(d34); DECL4(d35); DECL4(d36); DECL4(d37);

    uint32_t fa0,fa1,fa2,fa3, fa4,fa5,fa6,fa7;
    uint32_t fa8,fa9,faa,fab, fac,fad,fae,faf;
    uint32_t fb0,fb1,fb2,fb3, fb4,fb5,fb6,fb7;
    uint32_t fb8,fb9,fba,fbb, fbc,fbd,fbe,fbf;

#define LDSM_FA(off_) do {                                                    \
        LDSM4(fa0,fa1,fa2,fa3, aA_ + (off_));                                 \
        LDSM4(fa4,fa5,fa6,fa7, aA_ + (off_) + 16 * RSA);                      \
        LDSM4(fa8,fa9,faa,fab, aA_ + (off_) + 32 * RSA);                      \
        LDSM4(fac,fad,fae,faf, aA_ + (off_) + 48 * RSA);                      \
    } while (0)
#define LDSM_FB(off_) do {                                                    \
        LDSM4T(fb0,fb1,fb2,fb3, aB_ + (off_));                                \
        LDSM4T(fb4,fb5,fb6,fb7, aB_ + (off_) + 32);                           \
        LDSM4T(fb8,fb9,fba,fbb, aB_ + (off_) + 64);                           \
        LDSM4T(fbc,fbd,fbe,fbf, aB_ + (off_) + 96);                           \
    } while (0)

    // ---- prologue: fill buffer 0 -------------------------------------------
    LOADR_A;  STS_X(sbase, aoff, ALO_D);
    LOADR_B;  STS_X(sbase, boff, BLO_D);
    __syncthreads();

#pragma unroll 1
    for (int c = 0; c < NCH; c++) {
        uint32_t aA_ = sbase + (uint32_t)((c & 1) * STAGEB) + apos;
        uint32_t aB_ = sbase + (uint32_t)((c & 1) * STAGEB) + bpos;
        uint32_t sn_ = sbase + (uint32_t)(((c + 1) & 1) * STAGEB);
        bool more = (c + 1 < NCH);

        if (more) LOADR_A;               // LDG chunk c+1 A (latency under T2)
        LDSM_FA(0);                      // FA = A-hi
        LDSM_FB(BLO_D);                  // FB = B-lo
        TERMX();                         // T2 = Ahi x Blo
        if (more) { STS_X(sn_, aoff, ALO_D); LOADR_B; }
        LDSM_FB(0);                      // FB = B-hi
        TERMX();                         // T1 = Ahi x Bhi
        LDSM_FA(ALO_D);                  // FA = A-lo
        TERMX();                         // T3 = Alo x Bhi
        if (more) STS_X(sn_, boff, BLO_D);
        __syncthreads();
    }
#undef LDSM_FA
#undef LDSM_FB
#undef LOADR_A
#undef LOADR_B
#undef STS_X

    // ---- epilogue (R11-proven mapping) --------------------------------------
    int grp = lane >> 2, qid = lane & 3;
    int r0 = m0 + wm * 64 + grp;
    int colB = n0 + wn * 64 + qid * 2;
    const float* bvec = bias + (size_t)e * NTOT;

    if (FFN1) {
#define EP1(M, J) do {                                                        \
        int col_ = colB + (J) * 8;                                            \
        float b0_ = __ldg(bvec + col_), b1_ = __ldg(bvec + col_ + 1);         \
        int rL_ = r0 + (M) * 16;                                              \
        if (rL_ < cnt) {                                                      \
            float u0 = d##M##J##_0 + b0_, u1 = d##M##J##_1 + b1_;             \
            *(float2*)(g_H + (size_t)(base + rL_) * HID + col_) =             \
                make_float2(GELU(u0), GELU(u1));                              \
        }                                                                     \
        if (rL_ + 8 < cnt) {                                                  \
            float u0 = d##M##J##_2 + b0_, u1 = d##M##J##_3 + b1_;             \
            *(float2*)(g_H + (size_t)(base + rL_ + 8) * HID + col_) =         \
                make_float2(GELU(u0), GELU(u1));                              \
        }                                                                     \
    } while (0)
        EP1(0,0); EP1(0,1); EP1(0,2); EP1(0,3); EP1(0,4); EP1(0,5); EP1(0,6); EP1(0,7);
        EP1(1,0); EP1(1,1); EP1(1,2); EP1(1,3); EP1(1,4); EP1(1,5); EP1(1,6); EP1(1,7);
        EP1(2,0); EP1(2,1); EP1(2,2); EP1(2,3); EP1(2,4); EP1(2,5); EP1(2,6); EP1(2,7);
        EP1(3,0); EP1(3,1); EP1(3,2); EP1(3,3); EP1(3,4); EP1(3,5); EP1(3,6); EP1(3,7);
#undef EP1
    } else {
#define EP2(M, J, TK, WW, TKH, WWH) do {                                      \
        int col_ = colB + (J) * 8;                                            \
        float b0_ = __ldg(bvec + col_), b1_ = __ldg(bvec + col_ + 1);         \
        int rL_ = r0 + (M) * 16;                                              \
        if (rL_ < cnt) {                                                      \
            atomicAdd(out + (size_t)(TK) * DIM + col_,     (d##M##J##_0 + b0_) * (WW)); \
            atomicAdd(out + (size_t)(TK) * DIM + col_ + 1, (d##M##J##_1 + b1_) * (WW)); \
        }                                                                     \
        if (rL_ + 8 < cnt) {                                                  \
            atomicAdd(out + (size_t)(TKH) * DIM + col_,     (d##M##J##_2 + b0_) * (WWH)); \
            atomicAdd(out + (size_t)(TKH) * DIM + col_ + 1, (d##M##J##_3 + b1_) * (WWH)); \
        }                                                                     \
    } while (0)
#define EPM(M) do {                                                           \
        int rL_ = r0 + (M) * 16;                                              \
        int tkL_ = 0, tkH_ = 0; float wL_ = 0.f, wH_ = 0.f;                   \
        if (rL_ < cnt)     { tkL_ = g_tok[e*T + rL_];     wL_ = g_wt[e*T + rL_]; } \
        if (rL_ + 8 < cnt) { tkH_ = g_tok[e*T + rL_ + 8]; wH_ = g_wt[e*T + rL_ + 8]; } \
        EP2(M,0,tkL_,wL_,tkH_,wH_); EP2(M,1,tkL_,wL_,tkH_,wH_);               \
        EP2(M,2,tkL_,wL_,tkH_,wH_); EP2(M,3,tkL_,wL_,tkH_,wH_);               \
        EP2(M,4,tkL_,wL_,tkH_,wH_); EP2(M,5,tkL_,wL_,tkH_,wH_);               \
        EP2(M,6,tkL_,wL_,tkH_,wH_); EP2(M,7,tkL_,wL_,tkH_,wH_);               \
    } while (0)
        EPM(0); EPM(1); EPM(2); EPM(3);
#undef EPM
#undef EP2
    }
}

// ---------------------------------------------------------------------------
// Launch
// ---------------------------------------------------------------------------
extern "C" void kernel_launch(void* const* d_in, const int* in_sizes, int n_in,
                              void* d_out, int out_size) {
    const float* x  = (const float*)d_in[0];
    const float* gw = (const float*)d_in[1];
    const float* gb = (const float*)d_in[2];
    const float* W1 = (const float*)d_in[3];
    const float* b1 = (const float*)d_in[4];
    const float* W2 = (const float*)d_in[5];
    const float* b2 = (const float*)d_in[6];
    float* out = (float*)d_out;

    zero_kernel<<<2048, 256>>>(out);
    gate_kernel<<<T / 8, 256>>>(x, gw, gb, out + (size_t)T * DIM);
    offsets_kernel<<<1, 32>>>();

    moe_mma<true ><<<dim3(HID / BN, T / BM, NEXP), 128>>>(x, W1, b1, nullptr);
    moe_mma<false><<<dim3(DIM / BN, T / BM, NEXP), 128>>>(nullptr, W2, b2, out);
}